// round 4
// baseline (speedup 1.0000x reference)
#include <cuda_runtime.h>

// RoIAlign2D: features (4,256,96,96) f32, rois (1024,5) f32 -> out (1024,256,7,7) f32
// OUT_SIZE=7, SPATIAL_SCALE=0.0625, SAMPLE_NUM=2
//
// Mapping: one thread per output element, linear tid == output index
// ((k*C + c)*7 + ph)*7 + pw. Warp lanes share one (k,c) feature patch ->
// high L1 reuse; stores fully coalesced.

#define CC 256
#define HH 96
#define WW 96
#define SCALE 0.0625f

__global__ __launch_bounds__(256) void roi_align_kernel(
    const float* __restrict__ feat,
    const float* __restrict__ rois,
    float* __restrict__ out,
    int total)
{
    int tid = blockIdx.x * 256 + threadIdx.x;
    if (tid >= total) return;

    // Decompose: tid = ((k*CC + c)*7 + ph)*7 + pw
    int pw  = tid % 7;
    int t   = tid / 7;
    int ph  = t % 7;
    t      /= 7;
    int c   = t & (CC - 1);
    int k   = t >> 8;

    const float* r = rois + k * 5;
    int   b  = (int)__ldg(r);
    float x1 = __ldg(r + 1) * SCALE;
    float y1 = __ldg(r + 2) * SCALE;
    float x2 = __ldg(r + 3) * SCALE;
    float y2 = __ldg(r + 4) * SCALE;

    float bw = fmaxf(x2 - x1, 1.0f) * (1.0f / 7.0f);
    float bh = fmaxf(y2 - y1, 1.0f) * (1.0f / 7.0f);

    const float* fb = feat + (size_t)(b * CC + c) * (HH * WW);

    // Precompute x interpolation data for the 2 x-samples (shared across sy)
    int   xlo[2], xhi[2];
    float wxl[2], wxh[2];
    #pragma unroll
    for (int sx = 0; sx < 2; ++sx) {
        float offs = (float)pw + 0.25f + 0.5f * (float)sx;
        float xc   = x1 + bw * offs;
        bool  vx   = (xc >= -1.0f) && (xc <= (float)WW);
        float xcl  = fminf(fmaxf(xc, 0.0f), (float)(WW - 1));
        float xfl  = floorf(xcl);
        int   lo   = (int)xfl;
        xlo[sx] = lo;
        xhi[sx] = min(lo + 1, WW - 1);
        float fx = xcl - xfl;
        wxh[sx] = vx ? fx : 0.0f;
        wxl[sx] = vx ? (1.0f - fx) : 0.0f;
    }

    float acc = 0.0f;
    #pragma unroll
    for (int sy = 0; sy < 2; ++sy) {
        float offs = (float)ph + 0.25f + 0.5f * (float)sy;
        float yc   = y1 + bh * offs;
        bool  vy   = (yc >= -1.0f) && (yc <= (float)HH);
        float ycl  = fminf(fmaxf(yc, 0.0f), (float)(HH - 1));
        float yfl  = floorf(ycl);
        int   ylo  = (int)yfl;
        int   yhi  = min(ylo + 1, HH - 1);
        float fy   = ycl - yfl;
        float wyh  = vy ? fy : 0.0f;
        float wyl  = vy ? (1.0f - fy) : 0.0f;

        const float* rlo = fb + ylo * WW;
        const float* rhi = fb + yhi * WW;

        #pragma unroll
        for (int sx = 0; sx < 2; ++sx) {
            float vlo = wxl[sx] * __ldg(rlo + xlo[sx]) + wxh[sx] * __ldg(rlo + xhi[sx]);
            float vhi = wxl[sx] * __ldg(rhi + xlo[sx]) + wxh[sx] * __ldg(rhi + xhi[sx]);
            acc += wyl * vlo + wyh * vhi;
        }
    }

    out[tid] = acc * 0.25f;
}

extern "C" void kernel_launch(void* const* d_in, const int* in_sizes, int n_in,
                              void* d_out, int out_size)
{
    const float* feat = (const float*)d_in[0];
    const float* rois = (const float*)d_in[1];
    float*       out  = (float*)d_out;

    int total  = out_size;                 // K * C * 7 * 7
    int blocks = (total + 255) / 256;
    roi_align_kernel<<<blocks, 256>>>(feat, rois, out, total);
}